// round 4
// baseline (speedup 1.0000x reference)
#include <cuda_runtime.h>
#include <math_constants.h>

// 9x9 max dilation, -inf SAME border. Zero shared memory:
//  - vertical 9-max per column via van Herk (segment-8 suffix/prefix maxes),
//    entirely in registers, one float4 column-group per lane
//  - horizontal 9-max via warp shuffles of per-lane prefix/suffix maxes
//
// Warp-tile: 120 output cols (128 loaded incl. 4-halo each side) x 64 rows
// (72 rows loaded). Lanes 1..30 store; lanes 0/31 are halo providers.

#define IMG_W 1024
#define IMG_H 1024
#define TILE_X 120
#define TILE_Y 64
#define TILES_X 9              // ceil(1024/120)
#define TILES_Y (IMG_H / TILE_Y)
#define WPB 8
#define THREADS (WPB * 32)

__device__ __forceinline__ float4 max4(float4 a, float4 b) {
    return make_float4(fmaxf(a.x, b.x), fmaxf(a.y, b.y),
                       fmaxf(a.z, b.z), fmaxf(a.w, b.w));
}

__global__ __launch_bounds__(THREADS)
void dilate9_kernel(const float* __restrict__ in, float* __restrict__ out,
                    int n_tiles) {
    const int lane = threadIdx.x & 31;
    const int g = blockIdx.x * WPB + (threadIdx.x >> 5);
    if (g >= n_tiles) return;

    const int tz  = g / (TILES_X * TILES_Y);
    const int rem = g - tz * (TILES_X * TILES_Y);
    const int ty  = rem / TILES_X;
    const int tx  = rem - ty * TILES_X;

    const int gx  = tx * TILE_X - 4 + lane * 4;   // this lane's float4 column
    const int gy0 = ty * TILE_Y;
    const bool xok  = (gx >= 0) && (gx < IMG_W);  // aligned: fully in or out
    const bool stok = (lane >= 1) && (lane <= 30) && (gx >= 0) && (gx < IMG_W);

    const float NEG = -CUDART_INF_F;
    const float4 NEG4 = make_float4(NEG, NEG, NEG, NEG);

    const float* ip = in  + (long)tz * (IMG_W * IMG_H) + gx;
    float*       op = out + (long)tz * (IMG_W * IMG_H) + gx;

    float4 raw[8], S[8];

    // ---- prologue segment: rows gy0-4 .. gy0+3 (suffix maxes S) ----
    #pragma unroll
    for (int j = 0; j < 8; ++j) {
        const int z = gy0 - 4 + j;
        raw[j] = (xok && z >= 0) ? *(const float4*)(ip + (long)z * IMG_W)
                                 : NEG4;
    }
    S[7] = raw[7];
    #pragma unroll
    for (int j = 6; j >= 0; --j) S[j] = max4(raw[j], S[j + 1]);

    // ---- main: 8 segments of 8 rows ----
    for (int seg = 0; seg < TILE_Y / 8; ++seg) {
        const int zbase = gy0 + 4 + seg * 8;
        float4 P = NEG4;
        #pragma unroll
        for (int j = 0; j < 8; ++j) {
            const int z = zbase + j;
            const float4 r = (xok && z < IMG_H)
                             ? *(const float4*)(ip + (long)z * IMG_W) : NEG4;
            raw[j] = r;
            P = (j == 0) ? r : max4(P, r);
            const float4 v = max4(S[j], P);   // vertical 9-max, row y = z-4

            // horizontal 9-max: prefix/suffix maxes + neighbor shuffles
            const float p2 = fmaxf(v.x, v.y);
            const float p3 = fmaxf(p2, v.z);
            const float a  = fmaxf(p3, v.w);
            const float s2 = fmaxf(v.z, v.w);
            const float s3 = fmaxf(v.y, s2);
            const float l_s1 = __shfl_up_sync(0xffffffffu, v.w, 1);
            const float l_s2 = __shfl_up_sync(0xffffffffu, s2, 1);
            const float l_s3 = __shfl_up_sync(0xffffffffu, s3, 1);
            const float l_a  = __shfl_up_sync(0xffffffffu, a,  1);
            const float r_p1 = __shfl_down_sync(0xffffffffu, v.x, 1);
            const float r_p2 = __shfl_down_sync(0xffffffffu, p2,  1);
            const float r_p3 = __shfl_down_sync(0xffffffffu, p3,  1);
            const float r_a  = __shfl_down_sync(0xffffffffu, a,   1);
            float4 o;
            o.x = fmaxf(fmaxf(l_a,  a), r_p1);
            o.y = fmaxf(fmaxf(l_s3, a), r_p2);
            o.z = fmaxf(fmaxf(l_s2, a), r_p3);
            o.w = fmaxf(fmaxf(l_s1, a), r_a);

            if (stok) *(float4*)(op + (long)(zbase - 4 + j) * IMG_W) = o;
        }
        // suffix maxes of the segment just loaded
        S[7] = raw[7];
        #pragma unroll
        for (int j = 6; j >= 0; --j) S[j] = max4(raw[j], S[j + 1]);
    }
}

extern "C" void kernel_launch(void* const* d_in, const int* in_sizes, int n_in,
                              void* d_out, int out_size) {
    const float* in = (const float*)d_in[0];
    float* out = (float*)d_out;
    const int N = in_sizes[0] / (IMG_W * IMG_H);     // 16
    const int n_tiles = TILES_X * TILES_Y * N;       // 2304
    const int blocks = (n_tiles + WPB - 1) / WPB;    // 288
    dilate9_kernel<<<blocks, THREADS>>>(in, out, n_tiles);
}

// round 5
// speedup vs baseline: 1.3804x; 1.3804x over previous
#include <cuda_runtime.h>
#include <math_constants.h>

// 9x9 max dilation, -inf SAME border. Zero shared memory.
// Vertical 9-max via van Herk segment-8 (suffix S / prefix P), in-place S
// reuse (raw row overwrites S[j] after its last use -> 32 fewer registers).
// Horizontal 9-max via warp shuffles of per-lane prefix/suffix maxes.
//
// Warp-tile: 120 output cols (128 loaded incl. 4-halo) x 32 rows (40 loaded).
// 4608 warp-tiles total (~31 warps/SM) to cover DRAM latency.

#define IMG_W 1024
#define IMG_H 1024
#define TILE_X 120
#define TILE_Y 32
#define TILES_X 9              // ceil(1024/120)
#define TILES_Y (IMG_H / TILE_Y)   // 32
#define WPB 8
#define THREADS (WPB * 32)

__device__ __forceinline__ float4 max4(float4 a, float4 b) {
    return make_float4(fmaxf(a.x, b.x), fmaxf(a.y, b.y),
                       fmaxf(a.z, b.z), fmaxf(a.w, b.w));
}

__global__ __launch_bounds__(THREADS)
void dilate9_kernel(const float* __restrict__ in, float* __restrict__ out,
                    int n_tiles) {
    const int lane = threadIdx.x & 31;
    const int g = blockIdx.x * WPB + (threadIdx.x >> 5);
    if (g >= n_tiles) return;

    const int tz  = g / (TILES_X * TILES_Y);
    const int rem = g - tz * (TILES_X * TILES_Y);
    const int ty  = rem / TILES_X;
    const int tx  = rem - ty * TILES_X;

    const int gx  = tx * TILE_X - 4 + lane * 4;   // this lane's float4 column
    const int gy0 = ty * TILE_Y;
    const bool xok  = (gx >= 0) && (gx < IMG_W);  // aligned: fully in or out
    const bool stok = (lane >= 1) && (lane <= 30) && (gx >= 0) && (gx < IMG_W);

    const float NEG = -CUDART_INF_F;
    const float4 NEG4 = make_float4(NEG, NEG, NEG, NEG);

    const float* ip = in  + (long)tz * (IMG_W * IMG_H) + gx;
    float*       op = out + (long)tz * (IMG_W * IMG_H) + gx;

    float4 S[8];

    // ---- prologue segment: rows gy0-4 .. gy0+3 -> suffix maxes S ----
    #pragma unroll
    for (int j = 0; j < 8; ++j) {
        const int z = gy0 - 4 + j;
        S[j] = (xok && z >= 0) ? *(const float4*)(ip + (long)z * IMG_W)
                               : NEG4;
    }
    #pragma unroll
    for (int j = 6; j >= 0; --j) S[j] = max4(S[j], S[j + 1]);

    // ---- main: TILE_Y/8 segments of 8 rows ----
    #pragma unroll
    for (int seg = 0; seg < TILE_Y / 8; ++seg) {
        const int zbase = gy0 + 4 + seg * 8;
        float4 P = NEG4;
        #pragma unroll
        for (int j = 0; j < 8; ++j) {
            const int z = zbase + j;
            const float4 r = (xok && z < IMG_H)
                             ? *(const float4*)(ip + (long)z * IMG_W) : NEG4;
            P = (j == 0) ? r : max4(P, r);
            const float4 v = max4(S[j], P);   // vertical 9-max, row y = z-4
            S[j] = r;                          // S[j] dead after use -> reuse

            // horizontal 9-max: prefix/suffix maxes + neighbor shuffles
            const float p2 = fmaxf(v.x, v.y);
            const float p3 = fmaxf(p2, v.z);
            const float a  = fmaxf(p3, v.w);
            const float s2 = fmaxf(v.z, v.w);
            const float s3 = fmaxf(v.y, s2);
            const float l_s1 = __shfl_up_sync(0xffffffffu, v.w, 1);
            const float l_s2 = __shfl_up_sync(0xffffffffu, s2, 1);
            const float l_s3 = __shfl_up_sync(0xffffffffu, s3, 1);
            const float l_a  = __shfl_up_sync(0xffffffffu, a,  1);
            const float r_p1 = __shfl_down_sync(0xffffffffu, v.x, 1);
            const float r_p2 = __shfl_down_sync(0xffffffffu, p2,  1);
            const float r_p3 = __shfl_down_sync(0xffffffffu, p3,  1);
            const float r_a  = __shfl_down_sync(0xffffffffu, a,   1);
            float4 o;
            o.x = fmaxf(fmaxf(l_a,  a), r_p1);
            o.y = fmaxf(fmaxf(l_s3, a), r_p2);
            o.z = fmaxf(fmaxf(l_s2, a), r_p3);
            o.w = fmaxf(fmaxf(l_s1, a), r_a);

            if (stok) *(float4*)(op + (long)(zbase - 4 + j) * IMG_W) = o;
        }
        // S currently holds this segment's raw rows -> suffix maxes in place
        #pragma unroll
        for (int j = 6; j >= 0; --j) S[j] = max4(S[j], S[j + 1]);
    }
}

extern "C" void kernel_launch(void* const* d_in, const int* in_sizes, int n_in,
                              void* d_out, int out_size) {
    const float* in = (const float*)d_in[0];
    float* out = (float*)d_out;
    const int N = in_sizes[0] / (IMG_W * IMG_H);     // 16
    const int n_tiles = TILES_X * TILES_Y * N;       // 4608
    const int blocks = (n_tiles + WPB - 1) / WPB;    // 576
    dilate9_kernel<<<blocks, THREADS>>>(in, out, n_tiles);
}

// round 8
// speedup vs baseline: 1.7752x; 1.2861x over previous
#include <cuda_runtime.h>
#include <math_constants.h>

// 9x9 max dilation, -inf SAME border. Zero shared memory.
// Vertical 9-max via van Herk segment-8 (suffix S / prefix P) at float2 lane
// width (S[8] = 16 regs, halves register pressure vs float4 -> ~2x occupancy).
// Horizontal 9-max via warp shuffles: lane holds cols (2L, 2L+1);
//   a=max(v0,v1); m=max(a[-1],a,a[+1]); o0=max(m,a[-2],v0[+2]);
//   o1=max(m,v1[-2],a[+2]).
//
// Warp-tile: 56 output cols (64 loaded incl. 4-halo) x 32 rows (40 loaded).
// Lanes 2..29 store. 9728 warp-tiles.

#define IMG_W 1024
#define IMG_H 1024
#define TILE_X 56
#define TILE_Y 32
#define TILES_X 19                 // ceil(1024/56)
#define TILES_Y (IMG_H / TILE_Y)   // 32
#define WPB 8
#define THREADS (WPB * 32)

__device__ __forceinline__ float2 max2(float2 a, float2 b) {
    return make_float2(fmaxf(a.x, b.x), fmaxf(a.y, b.y));
}

__global__ __launch_bounds__(THREADS, 5)
void dilate9_kernel(const float* __restrict__ in, float* __restrict__ out,
                    int n_tiles) {
    const int lane = threadIdx.x & 31;
    const int g = blockIdx.x * WPB + (threadIdx.x >> 5);
    if (g >= n_tiles) return;

    const int tz  = g / (TILES_X * TILES_Y);
    const int rem = g - tz * (TILES_X * TILES_Y);
    const int ty  = rem / TILES_X;
    const int tx  = rem - ty * TILES_X;

    const int gx  = tx * TILE_X - 4 + lane * 2;   // this lane's float2 column
    const int gy0 = ty * TILE_Y;
    const bool xok  = (gx >= 0) && (gx < IMG_W);  // even: fully in or out
    const bool stok = (lane >= 2) && (lane <= 29) && (gx < IMG_W);

    const float NEG = -CUDART_INF_F;
    const float2 NEG2 = make_float2(NEG, NEG);

    const float* ip = in  + (long)tz * (IMG_W * IMG_H) + gx;
    float*       op = out + (long)tz * (IMG_W * IMG_H) + gx;

    float2 S[8];

    // ---- prologue segment: rows gy0-4 .. gy0+3 -> suffix maxes S ----
    #pragma unroll
    for (int j = 0; j < 8; ++j) {
        const int z = gy0 - 4 + j;
        S[j] = (xok && z >= 0) ? *(const float2*)(ip + (long)z * IMG_W)
                               : NEG2;
    }
    #pragma unroll
    for (int j = 6; j >= 0; --j) S[j] = max2(S[j], S[j + 1]);

    // ---- main: TILE_Y/8 segments of 8 rows ----
    #pragma unroll
    for (int seg = 0; seg < TILE_Y / 8; ++seg) {
        const int zbase = gy0 + 4 + seg * 8;
        float2 P = NEG2;
        #pragma unroll
        for (int j = 0; j < 8; ++j) {
            const int z = zbase + j;
            const float2 r = (xok && z < IMG_H)
                             ? *(const float2*)(ip + (long)z * IMG_W) : NEG2;
            P = (j == 0) ? r : max2(P, r);
            const float2 v = max2(S[j], P);   // vertical 9-max, row y = z-4
            S[j] = r;                          // S[j] dead after use -> reuse

            // horizontal 9-max via shuffles
            const float a    = fmaxf(v.x, v.y);
            const float a_m2 = __shfl_up_sync(0xffffffffu, a, 2);
            const float a_m1 = __shfl_up_sync(0xffffffffu, a, 1);
            const float a_p1 = __shfl_down_sync(0xffffffffu, a, 1);
            const float a_p2 = __shfl_down_sync(0xffffffffu, a, 2);
            const float v0p2 = __shfl_down_sync(0xffffffffu, v.x, 2);
            const float v1m2 = __shfl_up_sync(0xffffffffu, v.y, 2);
            const float m = fmaxf(fmaxf(a_m1, a), a_p1);
            float2 o;
            o.x = fmaxf(fmaxf(m, a_m2), v0p2);
            o.y = fmaxf(fmaxf(m, v1m2), a_p2);

            if (stok) *(float2*)(op + (long)(zbase - 4 + j) * IMG_W) = o;
        }
        // S currently holds this segment's raw rows -> suffix maxes in place
        #pragma unroll
        for (int j = 6; j >= 0; --j) S[j] = max2(S[j], S[j + 1]);
    }
}

extern "C" void kernel_launch(void* const* d_in, const int* in_sizes, int n_in,
                              void* d_out, int out_size) {
    const float* in = (const float*)d_in[0];
    float* out = (float*)d_out;
    const int N = in_sizes[0] / (IMG_W * IMG_H);     // 16
    const int n_tiles = TILES_X * TILES_Y * N;       // 9728
    const int blocks = (n_tiles + WPB - 1) / WPB;    // 1216
    dilate9_kernel<<<blocks, THREADS>>>(in, out, n_tiles);
}